// round 2
// baseline (speedup 1.0000x reference)
#include <cuda_runtime.h>
#include <math.h>
#include <string.h>

#ifndef M_PI
#define M_PI 3.14159265358979323846
#endif

// Problem geometry: IRREPS_L = [0]*32 + [1]*16 + [2]*8 + [3]*8 + [4]*4
// DIM = 32*1 + 16*3 + 8*5 + 8*7 + 4*9 = 212
#define NBLK 165            // sum of (2l+1)^2 over unique l = 1+9+25+49+81
#define DIMSZ 212
#define NW 1092             // total nonzero elements per batch matrix:
                            // 32*1 + 16*9 + 8*25 + 8*49 + 4*81

struct Consts {
    float A[NBLK];
    float Ainv[NBLK];
    unsigned char el[NBLK + 3];
    unsigned char ei[NBLK + 3];
    unsigned char ek[NBLK + 3];
    int   cum[5];            // {0,1,10,35,84}
    int   wdst[NW];          // destination offset within 212x212 matrix
    short wsrc[NW];          // source index within 165-float block array
};

__constant__ Consts cc;

// ---------------------------------------------------------------------------
// Scatter kernel: one CTA per batch element.
//  Stage A: sincos(m*angle) for m=0..4, three angles.
//  Stage B: M = (A * Zbeta) * Ainv      (165 threads, one element each)
//  Stage C: D = Zalpha * M * Zgamma     (165 threads, one element each)
//  Stage D: write ONLY the 1092 nonzero entries (output was pre-zeroed by
//           a cudaMemsetAsync node in the same graph).
// ---------------------------------------------------------------------------
__global__ __launch_bounds__(256) void wigner_scatter(
    const float* __restrict__ alpha,
    const float* __restrict__ beta,
    const float* __restrict__ gamma,
    float* __restrict__ out)
{
    __shared__ float s_tr[6][5];  // [ca, sa, cb, sb, cg, sg][m]
    __shared__ float sM[NBLK];
    __shared__ float sD[NBLK];

    const int b   = blockIdx.x;
    const int tid = threadIdx.x;

    if (tid < 15) {
        int which = tid / 5;
        int m     = tid - which * 5;
        float ang = (which == 0) ? alpha[b] : (which == 1) ? beta[b] : gamma[b];
        float s, c;
        sincosf((float)m * ang, &s, &c);
        s_tr[2 * which][m]     = c;
        s_tr[2 * which + 1][m] = s;
    }
    __syncthreads();

    if (tid < NBLK) {
        const int l = cc.el[tid], i = cc.ei[tid], k = cc.ek[tid];
        const int n = 2 * l + 1;
        const int ab = cc.cum[l];
        float acc = 0.f;
        for (int j = 0; j < n; ++j) {
            int mj = j - l;
            int am = mj < 0 ? -mj : mj;
            float cb = s_tr[2][am];
            float sb = (mj >= 0) ? s_tr[3][am] : -s_tr[3][am];
            // (A * Zbeta)[i,j] = A[i,j]*cos(m_j b) + A[i,n-1-j]*sin(m_j b)
            float az = cc.A[ab + i * n + j] * cb + cc.A[ab + i * n + (n - 1 - j)] * sb;
            acc += az * cc.Ainv[ab + j * n + k];
        }
        sM[ab + i * n + k] = acc;
    }
    __syncthreads();

    if (tid < NBLK) {
        const int l = cc.el[tid], i = cc.ei[tid], k = cc.ek[tid];
        const int n = 2 * l + 1;
        const int ab = cc.cum[l];
        const int ri = n - 1 - i, rk = n - 1 - k;
        const int mi = i - l, mk = k - l;
        const int ami = mi < 0 ? -mi : mi;
        const int amk = mk < 0 ? -mk : mk;
        float cai = s_tr[0][ami];
        float sai = (mi >= 0) ? s_tr[1][ami] : -s_tr[1][ami];
        float cgk = s_tr[4][amk];
        float sgk = (mk >= 0) ? s_tr[5][amk] : -s_tr[5][amk];
        float t0 = cai * sM[ab + i * n + k]  - sai * sM[ab + ri * n + k];
        float t1 = cai * sM[ab + i * n + rk] - sai * sM[ab + ri * n + rk];
        sD[ab + i * n + k] = t0 * cgk + t1 * sgk;
    }
    __syncthreads();

    float* ob = out + (size_t)b * (DIMSZ * DIMSZ);
    #pragma unroll 2
    for (int t = tid; t < NW; t += 256) {
        ob[cc.wdst[t]] = sD[cc.wsrc[t]];
    }
}

// ===========================================================================
// Host-side: compute the real-SH Wigner matrices of R = Rx(-90deg) exactly.
// The reference's lstsq is over a CONSISTENT system, so its solution is the
// exact Wigner matrix independent of the sample points; we reproduce it in
// double precision with deterministic Fibonacci-sphere points.
// ===========================================================================

static const int CNT[5]  = {32, 16, 8, 8, 4};
static const int CUMH[5] = {0, 1, 10, 35, 84};

static double dfactorial(int n) { double r = 1.0; for (int i = 2; i <= n; ++i) r *= (double)i; return r; }

static void alegendre(int l, double x, double* res) {
    for (int m = 0; m <= l; ++m) {
        double pmm = 1.0;
        if (m > 0) {
            double somx2 = sqrt(fmax(1.0 - x * x, 0.0));
            double fact = 1.0;
            for (int i = 0; i < m; ++i) { pmm = -pmm * fact * somx2; fact += 2.0; }
        }
        if (l == m) { res[m] = pmm; continue; }
        double pmmp1 = x * (2 * m + 1) * pmm;
        if (l == m + 1) { res[m] = pmmp1; continue; }
        double p0 = pmm, p1 = pmmp1, pll = 0.0;
        for (int ll = m + 2; ll <= l; ++ll) {
            pll = ((2 * ll - 1) * x * p1 - (ll + m - 1) * p0) / (ll - m);
            p0 = p1; p1 = pll;
        }
        res[m] = pll;
    }
}

static void rsh(int l, double x, double y, double z, double* out) {
    double phi = atan2(y, x);
    double P[5];
    alegendre(l, z, P);
    for (int m = -l; m <= l; ++m) {
        int am = m < 0 ? -m : m;
        double N = sqrt((2 * l + 1) / (4.0 * M_PI) * dfactorial(l - am) / dfactorial(l + am));
        double v;
        if (m == 0)      v = N * P[0];
        else if (m > 0)  v = sqrt(2.0) * N * P[am] * cos(m * phi);
        else             v = sqrt(2.0) * N * P[am] * sin(am * phi);
        out[m + l] = v;
    }
}

// Solve A X = B in place (B <- X). A is n x n, B is n x m. Partial pivoting.
static void gsolve(int n, int m, double* A, double* B) {
    for (int col = 0; col < n; ++col) {
        int piv = col;
        for (int r2 = col + 1; r2 < n; ++r2)
            if (fabs(A[r2 * n + col]) > fabs(A[piv * n + col])) piv = r2;
        if (piv != col) {
            for (int c2 = 0; c2 < n; ++c2) { double t = A[col * n + c2]; A[col * n + c2] = A[piv * n + c2]; A[piv * n + c2] = t; }
            for (int c2 = 0; c2 < m; ++c2) { double t = B[col * m + c2]; B[col * m + c2] = B[piv * m + c2]; B[piv * m + c2] = t; }
        }
        double d = A[col * n + col];
        for (int c2 = col; c2 < n; ++c2) A[col * n + c2] /= d;
        for (int c2 = 0; c2 < m; ++c2) B[col * m + c2] /= d;
        for (int r2 = 0; r2 < n; ++r2) {
            if (r2 == col) continue;
            double f = A[r2 * n + col];
            if (f == 0.0) continue;
            for (int c2 = col; c2 < n; ++c2) A[r2 * n + c2] -= f * A[col * n + c2];
            for (int c2 = 0; c2 < m; ++c2) B[r2 * m + c2] -= f * B[col * m + c2];
        }
    }
}

static void compute_wigner_consts(Consts& h) {
    const int NP = 512;
    static double pts[NP][3];
    const double ga = M_PI * (3.0 - sqrt(5.0));
    for (int i = 0; i < NP; ++i) {
        double z = 1.0 - 2.0 * (i + 0.5) / NP;
        double rr = sqrt(fmax(1.0 - z * z, 0.0));
        double ph = ga * i;
        pts[i][0] = rr * cos(ph); pts[i][1] = rr * sin(ph); pts[i][2] = z;
    }
    for (int l = 0; l < 5; ++l) {
        int n = 2 * l + 1;
        double G[81], C[81];
        memset(G, 0, sizeof(G)); memset(C, 0, sizeof(C));
        for (int p = 0; p < NP; ++p) {
            double Y[9], Yr[9];
            double x = pts[p][0], y = pts[p][1], z = pts[p][2];
            rsh(l, x, y, z, Y);
            // R = [[1,0,0],[0,0,1],[0,-1,0]]: (x,y,z) -> (x, z, -y)
            rsh(l, x, z, -y, Yr);
            for (int a = 0; a < n; ++a)
                for (int b2 = 0; b2 < n; ++b2) {
                    G[a * n + b2] += Y[a] * Y[b2];
                    C[a * n + b2] += Y[a] * Yr[b2];
                }
        }
        // Normal equations: G * Dt = C;  A = Dt^T
        double Gt[81]; memcpy(Gt, G, sizeof(double) * n * n);
        gsolve(n, n, Gt, C);               // C <- Dt
        double Ad[81];
        for (int a = 0; a < n; ++a)
            for (int b2 = 0; b2 < n; ++b2)
                Ad[a * n + b2] = C[b2 * n + a];
        double At[81]; memcpy(At, Ad, sizeof(double) * n * n);
        double I[81]; memset(I, 0, sizeof(I));
        for (int a = 0; a < n; ++a) I[a * n + a] = 1.0;
        gsolve(n, n, At, I);               // I <- A^{-1}
        for (int e = 0; e < n * n; ++e) {
            h.A[CUMH[l] + e]    = (float)Ad[e];
            h.Ainv[CUMH[l] + e] = (float)I[e];
        }
    }
}

static void build_tables(Consts& h) {
    int t = 0;
    for (int l = 0; l < 5; ++l) {
        int n = 2 * l + 1;
        for (int i = 0; i < n; ++i)
            for (int k = 0; k < n; ++k) { h.el[t] = (unsigned char)l; h.ei[t] = (unsigned char)i; h.ek[t] = (unsigned char)k; ++t; }
    }
    for (int l = 0; l < 5; ++l) h.cum[l] = CUMH[l];

    // Write table: every nonzero entry of the block-diagonal matrix.
    int off = 0, w = 0;
    for (int l = 0; l < 5; ++l) {
        int n = 2 * l + 1;
        for (int c = 0; c < CNT[l]; ++c) {
            for (int i = 0; i < n; ++i)
                for (int k = 0; k < n; ++k) {
                    h.wdst[w] = (off + i) * DIMSZ + (off + k);
                    h.wsrc[w] = (short)(CUMH[l] + i * n + k);
                    ++w;
                }
            off += n;
        }
    }
}

extern "C" void kernel_launch(void* const* d_in, const int* in_sizes, int n_in,
                              void* d_out, int out_size)
{
    static Consts h;
    static bool host_built = false;
    if (!host_built) {         // host-side constant precompute only; identical
        build_tables(h);       // data every call, device state re-written below
        compute_wigner_consts(h);
        host_built = true;
    }
    // Capturable nodes: H2D const copy, bulk memset of the output, scatter.
    cudaMemcpyToSymbolAsync(cc, &h, sizeof(Consts), 0, cudaMemcpyHostToDevice, 0);
    cudaMemsetAsync(d_out, 0, (size_t)out_size * sizeof(float), 0);

    const float* alpha = (const float*)d_in[0];
    const float* beta  = (const float*)d_in[1];
    const float* gamma = (const float*)d_in[2];
    int B = in_sizes[0];

    wigner_scatter<<<B, 256>>>(alpha, beta, gamma, (float*)d_out);
}

// round 3
// speedup vs baseline: 1.3810x; 1.3810x over previous
#include <cuda_runtime.h>
#include <math.h>
#include <string.h>

#ifndef M_PI
#define M_PI 3.14159265358979323846
#endif

// Problem geometry: IRREPS_L = [0]*32 + [1]*16 + [2]*8 + [3]*8 + [4]*4
// DIM = 32*1 + 16*3 + 8*5 + 8*7 + 4*9 = 212
#define NBLK 165            // sum of (2l+1)^2 over unique l = 1+9+25+49+81
#define DIMSZ 212
#define NW 1092             // nonzero elements per batch matrix

// --- Divergently-indexed tables live in GLOBAL memory (LDG path), not
// --- __constant__: per-lane divergent LDC serializes via replay (R2 lesson).
__device__ float         gA[NBLK];
__device__ float         gAinv[NBLK];
__device__ unsigned char gel[NBLK + 3];
__device__ unsigned char gei[NBLK + 3];
__device__ unsigned char gek[NBLK + 3];
__device__ int           gwdst[NW];
__device__ short         gwsrc[NW];

// Uniform-access scalars can stay in constant memory.
__constant__ int ccum[5];   // {0,1,10,35,84}

// ---------------------------------------------------------------------------
// Scatter kernel: one CTA per batch element. Output pre-zeroed by memset node.
// ---------------------------------------------------------------------------
__global__ __launch_bounds__(256) void wigner_scatter(
    const float* __restrict__ alpha,
    const float* __restrict__ beta,
    const float* __restrict__ gamma,
    float* __restrict__ out)
{
    __shared__ float s_tr[6][5];  // [ca, sa, cb, sb, cg, sg][m]
    __shared__ float sM[NBLK];
    __shared__ float sD[NBLK];

    const int b   = blockIdx.x;
    const int tid = threadIdx.x;

    if (tid < 15) {
        int which = tid / 5;
        int m     = tid - which * 5;
        float ang = (which == 0) ? alpha[b] : (which == 1) ? beta[b] : gamma[b];
        float s, c;
        sincosf((float)m * ang, &s, &c);
        s_tr[2 * which][m]     = c;
        s_tr[2 * which + 1][m] = s;
    }
    __syncthreads();

    if (tid < NBLK) {
        const int l = gel[tid], i = gei[tid], k = gek[tid];
        const int n = 2 * l + 1;
        const int ab = ccum[l];
        float acc = 0.f;
        for (int j = 0; j < n; ++j) {
            int mj = j - l;
            int am = mj < 0 ? -mj : mj;
            float cb = s_tr[2][am];
            float sb = (mj >= 0) ? s_tr[3][am] : -s_tr[3][am];
            float az = __ldg(&gA[ab + i * n + j]) * cb
                     + __ldg(&gA[ab + i * n + (n - 1 - j)]) * sb;
            acc += az * __ldg(&gAinv[ab + j * n + k]);
        }
        sM[ab + i * n + k] = acc;
    }
    __syncthreads();

    if (tid < NBLK) {
        const int l = gel[tid], i = gei[tid], k = gek[tid];
        const int n = 2 * l + 1;
        const int ab = ccum[l];
        const int ri = n - 1 - i, rk = n - 1 - k;
        const int mi = i - l, mk = k - l;
        const int ami = mi < 0 ? -mi : mi;
        const int amk = mk < 0 ? -mk : mk;
        float cai = s_tr[0][ami];
        float sai = (mi >= 0) ? s_tr[1][ami] : -s_tr[1][ami];
        float cgk = s_tr[4][amk];
        float sgk = (mk >= 0) ? s_tr[5][amk] : -s_tr[5][amk];
        float t0 = cai * sM[ab + i * n + k]  - sai * sM[ab + ri * n + k];
        float t1 = cai * sM[ab + i * n + rk] - sai * sM[ab + ri * n + rk];
        sD[ab + i * n + k] = t0 * cgk + t1 * sgk;
    }
    __syncthreads();

    float* ob = out + (size_t)b * (DIMSZ * DIMSZ);
    // NW = 1092; 256 threads -> iterations t, t+256, ..., fully unrolled-ish.
    #pragma unroll 5
    for (int t = tid; t < NW; t += 256) {
        int   d = __ldg(&gwdst[t]);
        short s = __ldg(&gwsrc[t]);
        ob[d] = sD[s];
    }
}

// ===========================================================================
// Host-side: compute the real-SH Wigner matrices of R = Rx(-90deg) exactly
// (double precision, deterministic points; lstsq of a consistent system).
// ===========================================================================

static const int CNT[5]  = {32, 16, 8, 8, 4};
static const int CUMH[5] = {0, 1, 10, 35, 84};

struct HostTables {
    float A[NBLK];
    float Ainv[NBLK];
    unsigned char el[NBLK + 3];
    unsigned char ei[NBLK + 3];
    unsigned char ek[NBLK + 3];
    int   wdst[NW];
    short wsrc[NW];
    int   cum[5];
};

static double dfactorial(int n) { double r = 1.0; for (int i = 2; i <= n; ++i) r *= (double)i; return r; }

static void alegendre(int l, double x, double* res) {
    for (int m = 0; m <= l; ++m) {
        double pmm = 1.0;
        if (m > 0) {
            double somx2 = sqrt(fmax(1.0 - x * x, 0.0));
            double fact = 1.0;
            for (int i = 0; i < m; ++i) { pmm = -pmm * fact * somx2; fact += 2.0; }
        }
        if (l == m) { res[m] = pmm; continue; }
        double pmmp1 = x * (2 * m + 1) * pmm;
        if (l == m + 1) { res[m] = pmmp1; continue; }
        double p0 = pmm, p1 = pmmp1, pll = 0.0;
        for (int ll = m + 2; ll <= l; ++ll) {
            pll = ((2 * ll - 1) * x * p1 - (ll + m - 1) * p0) / (ll - m);
            p0 = p1; p1 = pll;
        }
        res[m] = pll;
    }
}

static void rsh(int l, double x, double y, double z, double* out) {
    double phi = atan2(y, x);
    double P[5];
    alegendre(l, z, P);
    for (int m = -l; m <= l; ++m) {
        int am = m < 0 ? -m : m;
        double N = sqrt((2 * l + 1) / (4.0 * M_PI) * dfactorial(l - am) / dfactorial(l + am));
        double v;
        if (m == 0)      v = N * P[0];
        else if (m > 0)  v = sqrt(2.0) * N * P[am] * cos(m * phi);
        else             v = sqrt(2.0) * N * P[am] * sin(am * phi);
        out[m + l] = v;
    }
}

static void gsolve(int n, int m, double* A, double* B) {
    for (int col = 0; col < n; ++col) {
        int piv = col;
        for (int r2 = col + 1; r2 < n; ++r2)
            if (fabs(A[r2 * n + col]) > fabs(A[piv * n + col])) piv = r2;
        if (piv != col) {
            for (int c2 = 0; c2 < n; ++c2) { double t = A[col * n + c2]; A[col * n + c2] = A[piv * n + c2]; A[piv * n + c2] = t; }
            for (int c2 = 0; c2 < m; ++c2) { double t = B[col * m + c2]; B[col * m + c2] = B[piv * m + c2]; B[piv * m + c2] = t; }
        }
        double d = A[col * n + col];
        for (int c2 = col; c2 < n; ++c2) A[col * n + c2] /= d;
        for (int c2 = 0; c2 < m; ++c2) B[col * m + c2] /= d;
        for (int r2 = 0; r2 < n; ++r2) {
            if (r2 == col) continue;
            double f = A[r2 * n + col];
            if (f == 0.0) continue;
            for (int c2 = col; c2 < n; ++c2) A[r2 * n + c2] -= f * A[col * n + c2];
            for (int c2 = 0; c2 < m; ++c2) B[r2 * m + c2] -= f * B[col * m + c2];
        }
    }
}

static void compute_wigner_consts(HostTables& h) {
    const int NP = 512;
    static double pts[NP][3];
    const double ga = M_PI * (3.0 - sqrt(5.0));
    for (int i = 0; i < NP; ++i) {
        double z = 1.0 - 2.0 * (i + 0.5) / NP;
        double rr = sqrt(fmax(1.0 - z * z, 0.0));
        double ph = ga * i;
        pts[i][0] = rr * cos(ph); pts[i][1] = rr * sin(ph); pts[i][2] = z;
    }
    for (int l = 0; l < 5; ++l) {
        int n = 2 * l + 1;
        double G[81], C[81];
        memset(G, 0, sizeof(G)); memset(C, 0, sizeof(C));
        for (int p = 0; p < NP; ++p) {
            double Y[9], Yr[9];
            double x = pts[p][0], y = pts[p][1], z = pts[p][2];
            rsh(l, x, y, z, Y);
            rsh(l, x, z, -y, Yr);   // R = Rx: (x,y,z) -> (x, z, -y)
            for (int a = 0; a < n; ++a)
                for (int b2 = 0; b2 < n; ++b2) {
                    G[a * n + b2] += Y[a] * Y[b2];
                    C[a * n + b2] += Y[a] * Yr[b2];
                }
        }
        double Gt[81]; memcpy(Gt, G, sizeof(double) * n * n);
        gsolve(n, n, Gt, C);               // C <- Dt
        double Ad[81];
        for (int a = 0; a < n; ++a)
            for (int b2 = 0; b2 < n; ++b2)
                Ad[a * n + b2] = C[b2 * n + a];
        double At[81]; memcpy(At, Ad, sizeof(double) * n * n);
        double I[81]; memset(I, 0, sizeof(I));
        for (int a = 0; a < n; ++a) I[a * n + a] = 1.0;
        gsolve(n, n, At, I);               // I <- A^{-1}
        for (int e = 0; e < n * n; ++e) {
            h.A[CUMH[l] + e]    = (float)Ad[e];
            h.Ainv[CUMH[l] + e] = (float)I[e];
        }
    }
}

static void build_tables(HostTables& h) {
    int t = 0;
    for (int l = 0; l < 5; ++l) {
        int n = 2 * l + 1;
        for (int i = 0; i < n; ++i)
            for (int k = 0; k < n; ++k) { h.el[t] = (unsigned char)l; h.ei[t] = (unsigned char)i; h.ek[t] = (unsigned char)k; ++t; }
    }
    for (int l = 0; l < 5; ++l) h.cum[l] = CUMH[l];

    int off = 0, w = 0;
    for (int l = 0; l < 5; ++l) {
        int n = 2 * l + 1;
        for (int c = 0; c < CNT[l]; ++c) {
            for (int i = 0; i < n; ++i)
                for (int k = 0; k < n; ++k) {
                    h.wdst[w] = (off + i) * DIMSZ + (off + k);
                    h.wsrc[w] = (short)(CUMH[l] + i * n + k);
                    ++w;
                }
            off += n;
        }
    }
}

extern "C" void kernel_launch(void* const* d_in, const int* in_sizes, int n_in,
                              void* d_out, int out_size)
{
    static HostTables h;
    static bool host_built = false;
    if (!host_built) {
        build_tables(h);
        compute_wigner_consts(h);
        host_built = true;
    }
    // Capturable H2D memcpy nodes into __device__ / __constant__ symbols.
    cudaMemcpyToSymbolAsync(gA,    h.A,    sizeof(h.A),    0, cudaMemcpyHostToDevice, 0);
    cudaMemcpyToSymbolAsync(gAinv, h.Ainv, sizeof(h.Ainv), 0, cudaMemcpyHostToDevice, 0);
    cudaMemcpyToSymbolAsync(gel,   h.el,   sizeof(h.el),   0, cudaMemcpyHostToDevice, 0);
    cudaMemcpyToSymbolAsync(gei,   h.ei,   sizeof(h.ei),   0, cudaMemcpyHostToDevice, 0);
    cudaMemcpyToSymbolAsync(gek,   h.ek,   sizeof(h.ek),   0, cudaMemcpyHostToDevice, 0);
    cudaMemcpyToSymbolAsync(gwdst, h.wdst, sizeof(h.wdst), 0, cudaMemcpyHostToDevice, 0);
    cudaMemcpyToSymbolAsync(gwsrc, h.wsrc, sizeof(h.wsrc), 0, cudaMemcpyHostToDevice, 0);
    cudaMemcpyToSymbolAsync(ccum,  h.cum,  sizeof(h.cum),  0, cudaMemcpyHostToDevice, 0);

    // Bulk zero of the output through the HW memset path (~6.3 TB/s).
    cudaMemsetAsync(d_out, 0, (size_t)out_size * sizeof(float), 0);

    const float* alpha = (const float*)d_in[0];
    const float* beta  = (const float*)d_in[1];
    const float* gamma = (const float*)d_in[2];
    int B = in_sizes[0];

    wigner_scatter<<<B, 256>>>(alpha, beta, gamma, (float*)d_out);
}

// round 4
// speedup vs baseline: 2.1054x; 1.5246x over previous
#include <cuda_runtime.h>
#include <math.h>
#include <string.h>

#ifndef M_PI
#define M_PI 3.14159265358979323846
#endif

// Problem geometry: IRREPS_L = [0]*32 + [1]*16 + [2]*8 + [3]*8 + [4]*4
// DIM = 32*1 + 16*3 + 8*5 + 8*7 + 4*9 = 212
#define NBLK 165            // sum of (2l+1)^2 over unique l
#define DIMSZ 212
#define QPB 11236           // float4 quads per batch matrix (212*212/4)
#define NHOT_PAD 1024       // hot quads padded (actual = 432; dups idempotent)

struct GTab {
    float A[NBLK];
    float Ainv[NBLK];
    unsigned char el[NBLK + 3];
    unsigned char ei[NBLK + 3];
    unsigned char ek[NBLK + 3];
    unsigned char pad_[3];
    int cum[8];                 // {0,1,10,35,84,...}
    int          hdst[NHOT_PAD];   // quad index within 11236
    unsigned int hsrc[NHOT_PAD];   // 4 packed byte-indices into sD (165 => 0)
};
__device__ GTab gT;

// ---------------------------------------------------------------------------
// Single fused kernel: one CTA per batch element.
//  Stage A: sincos(m*angle), m=0..4, three angles (15 threads)
//  Stage B: M = (A * Zbeta) * Ainv      (165 threads)
//  Stage C: D = Zalpha * M * Zgamma     (165 threads)
//  Zero pass: stream 11236 coalesced float4 zeros (in-kernel memset)
//  __syncthreads (CTA fence: orders zero WAW before hot overwrite)
//  Hot pass: overwrite the 432 block-touching quads with gathered values
// ---------------------------------------------------------------------------
__global__ __launch_bounds__(256) void wigner_full(
    const float* __restrict__ alpha,
    const float* __restrict__ beta,
    const float* __restrict__ gamma,
    float4* __restrict__ out)
{
    __shared__ float s_tr[6][5];
    __shared__ float sM[NBLK];
    __shared__ float sD[NBLK + 3];

    const int b   = blockIdx.x;
    const int tid = threadIdx.x;

    if (tid < 15) {
        int which = tid / 5;
        int m     = tid - which * 5;
        float ang = (which == 0) ? alpha[b] : (which == 1) ? beta[b] : gamma[b];
        float s, c;
        sincosf((float)m * ang, &s, &c);
        s_tr[2 * which][m]     = c;
        s_tr[2 * which + 1][m] = s;
    }
    __syncthreads();

    if (tid < NBLK) {
        const int l = gT.el[tid], i = gT.ei[tid], k = gT.ek[tid];
        const int n = 2 * l + 1;
        const int ab = __ldg(&gT.cum[l]);
        float acc = 0.f;
        for (int j = 0; j < n; ++j) {
            int mj = j - l;
            int am = mj < 0 ? -mj : mj;
            float cb = s_tr[2][am];
            float sb = (mj >= 0) ? s_tr[3][am] : -s_tr[3][am];
            float az = __ldg(&gT.A[ab + i * n + j]) * cb
                     + __ldg(&gT.A[ab + i * n + (n - 1 - j)]) * sb;
            acc += az * __ldg(&gT.Ainv[ab + j * n + k]);
        }
        sM[ab + i * n + k] = acc;
    } else if (tid < NBLK + 3) {
        sD[tid] = 0.f;          // zero pad slot for partially-covered quads
    }
    __syncthreads();

    if (tid < NBLK) {
        const int l = gT.el[tid], i = gT.ei[tid], k = gT.ek[tid];
        const int n = 2 * l + 1;
        const int ab = __ldg(&gT.cum[l]);
        const int ri = n - 1 - i, rk = n - 1 - k;
        const int mi = i - l, mk = k - l;
        const int ami = mi < 0 ? -mi : mi;
        const int amk = mk < 0 ? -mk : mk;
        float cai = s_tr[0][ami];
        float sai = (mi >= 0) ? s_tr[1][ami] : -s_tr[1][ami];
        float cgk = s_tr[4][amk];
        float sgk = (mk >= 0) ? s_tr[5][amk] : -s_tr[5][amk];
        float t0 = cai * sM[ab + i * n + k]  - sai * sM[ab + ri * n + k];
        float t1 = cai * sM[ab + i * n + rk] - sai * sM[ab + ri * n + rk];
        sD[ab + i * n + k] = t0 * cgk + t1 * sgk;
    }

    // ---- Zero pass: coalesced streaming zeros over the whole 212x212 tile.
    float4* ob = out + (size_t)b * QPB;
    const float4 z = make_float4(0.f, 0.f, 0.f, 0.f);
    #pragma unroll
    for (int u = 0; u < 43; ++u)        // 43*256 = 11008
        ob[u * 256 + tid] = z;
    if (tid < QPB - 43 * 256)           // remainder 228
        ob[43 * 256 + tid] = z;

    // Orders the zero-pass global WAW before the hot overwrite (CTA scope),
    // and makes sD (stage C) visible to all threads.
    __syncthreads();

    // ---- Hot pass: overwrite block-touching quads.
    #pragma unroll
    for (int u = 0; u < NHOT_PAD / 256; ++u) {
        int t = u * 256 + tid;
        int          d = __ldg(&gT.hdst[t]);
        unsigned int s = __ldg(&gT.hsrc[t]);
        float4 v = make_float4(sD[s & 255],
                               sD[(s >> 8) & 255],
                               sD[(s >> 16) & 255],
                               sD[s >> 24]);
        ob[d] = v;
    }
}

// ===========================================================================
// Host-side: exact Wigner matrices of Rx (double precision, deterministic
// points; lstsq of a consistent system) + geometry tables.
// ===========================================================================

static const int CNT[5]  = {32, 16, 8, 8, 4};
static const int CUMH[5] = {0, 1, 10, 35, 84};

static double dfactorial(int n) { double r = 1.0; for (int i = 2; i <= n; ++i) r *= (double)i; return r; }

static void alegendre(int l, double x, double* res) {
    for (int m = 0; m <= l; ++m) {
        double pmm = 1.0;
        if (m > 0) {
            double somx2 = sqrt(fmax(1.0 - x * x, 0.0));
            double fact = 1.0;
            for (int i = 0; i < m; ++i) { pmm = -pmm * fact * somx2; fact += 2.0; }
        }
        if (l == m) { res[m] = pmm; continue; }
        double pmmp1 = x * (2 * m + 1) * pmm;
        if (l == m + 1) { res[m] = pmmp1; continue; }
        double p0 = pmm, p1 = pmmp1, pll = 0.0;
        for (int ll = m + 2; ll <= l; ++ll) {
            pll = ((2 * ll - 1) * x * p1 - (ll + m - 1) * p0) / (ll - m);
            p0 = p1; p1 = pll;
        }
        res[m] = pll;
    }
}

static void rsh(int l, double x, double y, double z, double* out) {
    double phi = atan2(y, x);
    double P[5];
    alegendre(l, z, P);
    for (int m = -l; m <= l; ++m) {
        int am = m < 0 ? -m : m;
        double N = sqrt((2 * l + 1) / (4.0 * M_PI) * dfactorial(l - am) / dfactorial(l + am));
        double v;
        if (m == 0)      v = N * P[0];
        else if (m > 0)  v = sqrt(2.0) * N * P[am] * cos(m * phi);
        else             v = sqrt(2.0) * N * P[am] * sin(am * phi);
        out[m + l] = v;
    }
}

static void gsolve(int n, int m, double* A, double* B) {
    for (int col = 0; col < n; ++col) {
        int piv = col;
        for (int r2 = col + 1; r2 < n; ++r2)
            if (fabs(A[r2 * n + col]) > fabs(A[piv * n + col])) piv = r2;
        if (piv != col) {
            for (int c2 = 0; c2 < n; ++c2) { double t = A[col * n + c2]; A[col * n + c2] = A[piv * n + c2]; A[piv * n + c2] = t; }
            for (int c2 = 0; c2 < m; ++c2) { double t = B[col * m + c2]; B[col * m + c2] = B[piv * m + c2]; B[piv * m + c2] = t; }
        }
        double d = A[col * n + col];
        for (int c2 = col; c2 < n; ++c2) A[col * n + c2] /= d;
        for (int c2 = 0; c2 < m; ++c2) B[col * m + c2] /= d;
        for (int r2 = 0; r2 < n; ++r2) {
            if (r2 == col) continue;
            double f = A[r2 * n + col];
            if (f == 0.0) continue;
            for (int c2 = col; c2 < n; ++c2) A[r2 * n + c2] -= f * A[col * n + c2];
            for (int c2 = 0; c2 < m; ++c2) B[r2 * m + c2] -= f * B[col * m + c2];
        }
    }
}

static void compute_wigner_consts(GTab& h) {
    const int NP = 512;
    static double pts[NP][3];
    const double ga = M_PI * (3.0 - sqrt(5.0));
    for (int i = 0; i < NP; ++i) {
        double z = 1.0 - 2.0 * (i + 0.5) / NP;
        double rr = sqrt(fmax(1.0 - z * z, 0.0));
        double ph = ga * i;
        pts[i][0] = rr * cos(ph); pts[i][1] = rr * sin(ph); pts[i][2] = z;
    }
    for (int l = 0; l < 5; ++l) {
        int n = 2 * l + 1;
        double G[81], C[81];
        memset(G, 0, sizeof(G)); memset(C, 0, sizeof(C));
        for (int p = 0; p < NP; ++p) {
            double Y[9], Yr[9];
            double x = pts[p][0], y = pts[p][1], z = pts[p][2];
            rsh(l, x, y, z, Y);
            rsh(l, x, z, -y, Yr);   // R = Rx: (x,y,z) -> (x, z, -y)
            for (int a = 0; a < n; ++a)
                for (int b2 = 0; b2 < n; ++b2) {
                    G[a * n + b2] += Y[a] * Y[b2];
                    C[a * n + b2] += Y[a] * Yr[b2];
                }
        }
        double Gt[81]; memcpy(Gt, G, sizeof(double) * n * n);
        gsolve(n, n, Gt, C);               // C <- Dt
        double Ad[81];
        for (int a = 0; a < n; ++a)
            for (int b2 = 0; b2 < n; ++b2)
                Ad[a * n + b2] = C[b2 * n + a];
        double At[81]; memcpy(At, Ad, sizeof(double) * n * n);
        double I[81]; memset(I, 0, sizeof(I));
        for (int a = 0; a < n; ++a) I[a * n + a] = 1.0;
        gsolve(n, n, At, I);               // I <- A^{-1}
        for (int e = 0; e < n * n; ++e) {
            h.A[CUMH[l] + e]    = (float)Ad[e];
            h.Ainv[CUMH[l] + e] = (float)I[e];
        }
    }
}

static void build_tables(GTab& h) {
    int t = 0;
    for (int l = 0; l < 5; ++l) {
        int n = 2 * l + 1;
        for (int i = 0; i < n; ++i)
            for (int k = 0; k < n; ++k) { h.el[t] = (unsigned char)l; h.ei[t] = (unsigned char)i; h.ek[t] = (unsigned char)k; ++t; }
    }
    for (int l = 0; l < 5; ++l) h.cum[l] = CUMH[l];
    for (int l = 5; l < 8; ++l) h.cum[l] = 0;

    // Hot quad table: for every row of every irrep block, the float4 quads
    // (groups of 4 columns) that intersect the block.
    int off = 0, row = 0, w = 0;
    for (int l = 0; l < 5; ++l) {
        int n = 2 * l + 1;
        for (int c = 0; c < CNT[l]; ++c) {
            for (int i = 0; i < n; ++i) {
                int qlo = off / 4;
                int qhi = (off + n - 1) / 4;
                for (int q = qlo; q <= qhi && w < NHOT_PAD; ++q) {
                    unsigned int packed = 0;
                    for (int j = 0; j < 4; ++j) {
                        int col = q * 4 + j;
                        unsigned int src;
                        if (col >= off && col < off + n)
                            src = (unsigned int)(CUMH[l] + i * n + (col - off));
                        else
                            src = NBLK;   // sD[165] == 0
                        packed |= src << (8 * j);
                    }
                    h.hdst[w] = row * (DIMSZ / 4) + q;
                    h.hsrc[w] = packed;
                    ++w;
                }
                ++row;
            }
            off += n;
        }
    }
    // Pad with duplicates of entry 0 (idempotent re-writes).
    for (; w < NHOT_PAD; ++w) { h.hdst[w] = h.hdst[0]; h.hsrc[w] = h.hsrc[0]; }
}

extern "C" void kernel_launch(void* const* d_in, const int* in_sizes, int n_in,
                              void* d_out, int out_size)
{
    static GTab h;
    static bool host_built = false;
    if (!host_built) {
        memset(&h, 0, sizeof(h));
        build_tables(h);
        compute_wigner_consts(h);
        host_built = true;
    }
    // Single capturable H2D memcpy node for all tables.
    cudaMemcpyToSymbolAsync(gT, &h, sizeof(GTab), 0, cudaMemcpyHostToDevice, 0);

    const float* alpha = (const float*)d_in[0];
    const float* beta  = (const float*)d_in[1];
    const float* gamma = (const float*)d_in[2];
    int B = in_sizes[0];

    wigner_full<<<B, 256>>>(alpha, beta, gamma, (float4*)d_out);
}